// round 5
// baseline (speedup 1.0000x reference)
#include <cuda_runtime.h>
#include <cstdint>
#include <math.h>

#define NTOK   4096
#define DMODEL 1024
#define DHID   256
#define NHEADS 4
#define HDIM   256

// ---------------- scratch (__device__ globals; no allocation allowed) -------
__device__ float    g_h  [NTOK * DHID];
__device__ int      g_mask[NTOK];
__device__ float    g_ctx[NTOK * DMODEL];
__device__ float    g_w1t[DHID * DMODEL];
__device__ float    g_wqt[DMODEL * DMODEL];
__device__ float    g_wkt[DMODEL * DMODEL];
__device__ float    g_wvt[DMODEL * DMODEL];
__device__ float    g_wot[DMODEL * DMODEL];
// bf16 hi/lo planes (u32 = 2 bf16)
__device__ uint32_t g_qph[NTOK * 512], g_qpl[NTOK * 512];
__device__ uint32_t g_kph[NTOK * 512], g_kpl[NTOK * 512];
__device__ uint32_t g_vph[NTOK * 512], g_vpl[NTOK * 512];
__device__ uint32_t g_vth[DMODEL * 2048], g_vtl[DMODEL * 2048];

// ---------------- bf16 helpers ----------------------------------------------
__device__ __forceinline__ uint32_t pack2(float x0, float x1) {
    uint32_t r;
    asm("cvt.rn.bf16x2.f32 %0, %1, %2;" : "=r"(r) : "f"(x1), "f"(x0));
    return r;
}
__device__ __forceinline__ void split2(float x0, float x1,
                                       uint32_t& h, uint32_t& l) {
    uint32_t hb = pack2(x0, x1);
    float f0 = __uint_as_float(hb << 16);
    float f1 = __uint_as_float(hb & 0xffff0000u);
    l = pack2(x0 - f0, x1 - f1);
    h = hb;
}
__device__ __forceinline__ void mma16816(float* c, const uint32_t* a,
                                         const uint32_t* b) {
    asm volatile(
        "mma.sync.aligned.m16n8k16.row.col.f32.bf16.bf16.f32 "
        "{%0,%1,%2,%3}, {%4,%5,%6,%7}, {%8,%9}, {%0,%1,%2,%3};"
        : "+f"(c[0]), "+f"(c[1]), "+f"(c[2]), "+f"(c[3])
        : "r"(a[0]), "r"(a[1]), "r"(a[2]), "r"(a[3]), "r"(b[0]), "r"(b[1]));
}
__device__ __forceinline__ uint32_t smem_u32(const void* p) {
    uint32_t a;
    asm("{ .reg .u64 t; cvta.to.shared.u64 t, %1; cvt.u32.u64 %0, t; }"
        : "=r"(a) : "l"(p));
    return a;
}
__device__ __forceinline__ void cp16(uint32_t dst, const void* src) {
    asm volatile("cp.async.cg.shared.global [%0], [%1], 16;"
                 :: "r"(dst), "l"(src));
}
#define CP_COMMIT() asm volatile("cp.async.commit_group;" ::: "memory")
#define CP_WAIT0()  asm volatile("cp.async.wait_group 0;" ::: "memory")
#define CP_WAIT1()  asm volatile("cp.async.wait_group 1;" ::: "memory")

// ---------------- unified 3xBF16 tensor-core GEMM ---------------------------
// D[M,N] = A[M,K] @ B[N,K]^T (+ epilogue). CTA 128x128, K-chunk 32, 8 warps.
enum { EPI_RAW = 0, EPI_BIAS, EPI_RELU, EPI_QSCALE, EPI_ROWMASK };

#define SROW   20
#define STG_U  (128 * SROW)
#define STG_B  (4 * STG_U * 4)
#define SMEM_BYTES (2 * STG_B)

__device__ __forceinline__ void ldg_chunk(const float* __restrict__ Arow,
                                          int lda,
                                          const float* __restrict__ Brow,
                                          int ldb, int k0, int tid,
                                          float4* av, float4* bv) {
#pragma unroll
    for (int i = 0; i < 4; i++) {
        int idx = tid + i * 256;
        int r = idx >> 3, c4 = idx & 7;
        av[i] = *(const float4*)(Arow + (long)r * lda + k0 + c4 * 4);
        bv[i] = *(const float4*)(Brow + (long)r * ldb + k0 + c4 * 4);
    }
}
__device__ __forceinline__ void sts_chunk(uint32_t* st, int tid,
                                          const float4* av, const float4* bv) {
    uint32_t* Ah = st;
    uint32_t* Al = st + STG_U;
    uint32_t* Bh = st + 2 * STG_U;
    uint32_t* Bl = st + 3 * STG_U;
#pragma unroll
    for (int i = 0; i < 4; i++) {
        int idx = tid + i * 256;
        int r = idx >> 3, c4 = idx & 7;
        uint32_t h01, l01, h23, l23;
        split2(av[i].x, av[i].y, h01, l01);
        split2(av[i].z, av[i].w, h23, l23);
        int o = r * SROW + c4 * 2;
        Ah[o] = h01; Ah[o + 1] = h23;
        Al[o] = l01; Al[o + 1] = l23;
        split2(bv[i].x, bv[i].y, h01, l01);
        split2(bv[i].z, bv[i].w, h23, l23);
        Bh[o] = h01; Bh[o + 1] = h23;
        Bl[o] = l01; Bl[o + 1] = l23;
    }
}

template <int EPI, int WBF>
__global__ __launch_bounds__(256, 1) void gemm_bf(
    const float* __restrict__ A, int lda,
    const float* __restrict__ B, int ldb,
    float* __restrict__ C, uint32_t* __restrict__ Ch,
    uint32_t* __restrict__ Cl, int ldc,
    int K, const float* __restrict__ bias,
    const int* __restrict__ mask, float scale)
{
    extern __shared__ __align__(16) char smem[];
    const int tid = threadIdx.x;
    const int wid = tid >> 5, lane = tid & 31;
    const int wm = wid & 3, wn = wid >> 2;
    const int qr = lane >> 2, qc = lane & 3;
    const int bm = blockIdx.y * 128, bn = blockIdx.x * 128;

    const float* Arow = A + (long)bm * lda;
    const float* Brow = B + (long)bn * ldb;

    float acc[2][8][4];
#pragma unroll
    for (int mf = 0; mf < 2; mf++)
#pragma unroll
        for (int nf = 0; nf < 8; nf++)
#pragma unroll
            for (int j = 0; j < 4; j++) acc[mf][nf][j] = 0.f;

    const int nc = K / 32;
    float4 av[4], bv[4];
    ldg_chunk(Arow, lda, Brow, ldb, 0, tid, av, bv);
    sts_chunk((uint32_t*)smem, tid, av, bv);
    __syncthreads();

    const int arow0 = wm * 32 + qr;
    const int brow0 = wn * 64 + qr;

    for (int c = 0; c < nc; c++) {
        if (c + 1 < nc)
            ldg_chunk(Arow, lda, Brow, ldb, (c + 1) * 32, tid, av, bv);
        uint32_t* st = (uint32_t*)(smem + (c & 1) * STG_B);
        const uint32_t* Ah = st;
        const uint32_t* Al = st + STG_U;
        const uint32_t* Bh = st + 2 * STG_U;
        const uint32_t* Bl = st + 3 * STG_U;
#pragma unroll
        for (int kk = 0; kk < 2; kk++) {
            const int kof = kk * 8 + qc;
            uint32_t ah[2][4], al[2][4], bh[8][2], bl[8][2];
#pragma unroll
            for (int mf = 0; mf < 2; mf++) {
                int base = (arow0 + mf * 16) * SROW + kof;
                ah[mf][0] = Ah[base];
                ah[mf][1] = Ah[base + 8 * SROW];
                ah[mf][2] = Ah[base + 4];
                ah[mf][3] = Ah[base + 8 * SROW + 4];
                al[mf][0] = Al[base];
                al[mf][1] = Al[base + 8 * SROW];
                al[mf][2] = Al[base + 4];
                al[mf][3] = Al[base + 8 * SROW + 4];
            }
#pragma unroll
            for (int nf = 0; nf < 8; nf++) {
                int base = (brow0 + nf * 8) * SROW + kof;
                bh[nf][0] = Bh[base];
                bh[nf][1] = Bh[base + 4];
                bl[nf][0] = Bl[base];
                bl[nf][1] = Bl[base + 4];
            }
#pragma unroll
            for (int mf = 0; mf < 2; mf++)
#pragma unroll
                for (int nf = 0; nf < 8; nf++) {
                    mma16816(acc[mf][nf], ah[mf], bh[nf]);
                    mma16816(acc[mf][nf], ah[mf], bl[nf]);
                    mma16816(acc[mf][nf], al[mf], bh[nf]);
                }
        }
        __syncthreads();
        if (c + 1 < nc) {
            sts_chunk((uint32_t*)(smem + ((c + 1) & 1) * STG_B), tid, av, bv);
            __syncthreads();
        }
    }

#pragma unroll
    for (int mf = 0; mf < 2; mf++) {
        const int r0 = bm + wm * 32 + mf * 16 + qr;
        const int r1 = r0 + 8;
        int keep0 = 1, keep1 = 1;
        if (EPI == EPI_ROWMASK) { keep0 = mask[r0]; keep1 = mask[r1]; }
#pragma unroll
        for (int nf = 0; nf < 8; nf++) {
            const int cc = bn + wn * 64 + nf * 8 + qc * 2;
            float v0 = acc[mf][nf][0], v1 = acc[mf][nf][1];
            float v2 = acc[mf][nf][2], v3 = acc[mf][nf][3];
            if (EPI != EPI_RAW) {
                float b0 = bias[cc], b1 = bias[cc + 1];
                v0 += b0; v1 += b1; v2 += b0; v3 += b1;
            }
            if (EPI == EPI_RELU) {
                v0 = fmaxf(v0, 0.f); v1 = fmaxf(v1, 0.f);
                v2 = fmaxf(v2, 0.f); v3 = fmaxf(v3, 0.f);
            }
            if (EPI == EPI_QSCALE) {
                v0 *= scale; v1 *= scale; v2 *= scale; v3 *= scale;
            }
            if (EPI == EPI_ROWMASK) {
                if (!keep0) { v0 = 0.f; v1 = 0.f; }
                if (!keep1) { v2 = 0.f; v3 = 0.f; }
            }
            if (WBF) {
                uint32_t h01, l01;
                split2(v0, v1, h01, l01);
                Ch[(long)r0 * (ldc >> 1) + (cc >> 1)] = h01;
                Cl[(long)r0 * (ldc >> 1) + (cc >> 1)] = l01;
                split2(v2, v3, h01, l01);
                Ch[(long)r1 * (ldc >> 1) + (cc >> 1)] = h01;
                Cl[(long)r1 * (ldc >> 1) + (cc >> 1)] = l01;
            } else {
                float2 o0 = {v0, v1}, o1 = {v2, v3};
                *(float2*)&C[(long)r0 * ldc + cc] = o0;
                *(float2*)&C[(long)r1 * ldc + cc] = o1;
            }
        }
    }
}

// ---------------- transposes -------------------------------------------------
__global__ void transpose_k(const float* __restrict__ in, float* __restrict__ out,
                            int R, int C)
{
    __shared__ float t[32][33];
    const int bx = blockIdx.x * 32, by = blockIdx.y * 32;
#pragma unroll
    for (int j = 0; j < 32; j += 8)
        t[threadIdx.y + j][threadIdx.x] =
            in[(long)(by + threadIdx.y + j) * C + bx + threadIdx.x];
    __syncthreads();
#pragma unroll
    for (int j = 0; j < 32; j += 8)
        out[(long)(bx + threadIdx.y + j) * R + by + threadIdx.x] =
            t[threadIdx.x][threadIdx.y + j];
}

// transpose bf16 planes: in [R][C] u16 -> out [C][R] u16;  z picks hi/lo
__global__ void transpose_bf(const uint16_t* __restrict__ inh,
                             const uint16_t* __restrict__ inl,
                             uint16_t* __restrict__ outh,
                             uint16_t* __restrict__ outl, int R, int C)
{
    __shared__ uint16_t t[32][34];
    const uint16_t* in = blockIdx.z ? inl : inh;
    uint16_t* out = blockIdx.z ? outl : outh;
    const int bx = blockIdx.x * 32, by = blockIdx.y * 32;
#pragma unroll
    for (int j = 0; j < 32; j += 8)
        t[threadIdx.y + j][threadIdx.x] =
            in[(long)(by + threadIdx.y + j) * C + bx + threadIdx.x];
    __syncthreads();
#pragma unroll
    for (int j = 0; j < 32; j += 8)
        out[(long)(bx + threadIdx.y + j) * R + by + threadIdx.x] =
            t[threadIdx.x][threadIdx.y + j];
}

// ---------------- mask: sigmoid(h @ w2 + b2) > 0.15 --------------------------
__global__ void score_k(const float* __restrict__ h, const float* __restrict__ w2,
                        const float* __restrict__ b2, int* __restrict__ mask)
{
    const int warp = (blockIdx.x * blockDim.x + threadIdx.x) >> 5;
    const int lane = threadIdx.x & 31;
    if (warp >= NTOK) return;
    const float* hr = h + warp * DHID;
    float s = 0.f;
#pragma unroll
    for (int i = 0; i < DHID / 32; i++)
        s += hr[lane + i * 32] * w2[lane + i * 32];
#pragma unroll
    for (int o = 16; o; o >>= 1) s += __shfl_xor_sync(0xffffffffu, s, o);
    if (lane == 0) {
        float sig = 1.0f / (1.0f + expf(-(s + b2[0])));
        mask[warp] = (sig > 0.15f) ? 1 : 0;
    }
}

// ---------------- fused flash attention (3xBF16 HMMA) ------------------------
// CTA: 64 queries x 1 head. 8 warps: wm(2) x wn(4).
// smem (u32): Q[2][64][132] | K[2stg][2pl][128][20] | P[2pl][64][68] |
//             V[2stg][2pl][64][68] | m,l,a[64] | red[4][64] | mask[128]
#define FL_QU   (64 * 132)
#define FL_KU   (128 * 20)
#define FL_PU   (64 * 68)
#define FL_VU   (64 * 68)
#define FL_SMEM_U32 (2*FL_QU + 4*FL_KU + 2*FL_PU + 4*FL_VU + 3*64 + 256 + 128)
#define FL_SMEM_B   (FL_SMEM_U32 * 4)

__global__ __launch_bounds__(256, 1) void flash_k(
    const uint32_t* __restrict__ qh, const uint32_t* __restrict__ qlp,
    const uint32_t* __restrict__ kh, const uint32_t* __restrict__ klp,
    const uint32_t* __restrict__ vh, const uint32_t* __restrict__ vlp,
    const int* __restrict__ mask, float* __restrict__ ctx)
{
    extern __shared__ __align__(16) uint32_t sm[];
    uint32_t* Qh = sm;
    uint32_t* Ql = Qh + FL_QU;
    uint32_t* Kb = Ql + FL_QU;            // [2][2][128][20]
    uint32_t* Pb = Kb + 4 * FL_KU;        // [2][64][68]
    uint32_t* Vb = Pb + 2 * FL_PU;        // [2][2][64][68]
    float* mS = (float*)(Vb + 4 * FL_VU);
    float* lS = mS + 64;
    float* aS = lS + 64;
    float* red = aS + 64;                 // [4][64]
    int* mk = (int*)(red + 256);          // [128]

    const int tid = threadIdx.x, wid = tid >> 5, lane = tid & 31;
    const int wm = wid >> 2, wn = wid & 3;
    const int qr = lane >> 2, qc = lane & 3;
    const int q0 = blockIdx.x * 64, h = blockIdx.y;

    // ---- load Q (both planes): 64 rows x 32 float4 x 2 planes = 4096 cp16 ----
#pragma unroll
    for (int i = 0; i < 16; i++) {
        int idx = tid + i * 256;
        int pl = idx >> 11, j = idx & 2047;
        int r = j >> 5, c4 = j & 31;
        const uint32_t* src = (pl ? qlp : qh) +
                              (size_t)(q0 + r) * 512 + h * 128 + c4 * 4;
        uint32_t* dst = (pl ? Ql : Qh) + r * 132 + c4 * 4;
        cp16(smem_u32(dst), src);
    }
    CP_COMMIT();
    if (tid < 64) { mS[tid] = -3.0e38f; lS[tid] = 0.f; }

    float accO[2][8][4];
#pragma unroll
    for (int mf = 0; mf < 2; mf++)
#pragma unroll
        for (int g = 0; g < 8; g++)
#pragma unroll
            for (int j = 0; j < 4; j++) accO[mf][g][j] = 0.f;

    for (int kt = 0; kt < NTOK / 128; kt++) {
        const int k0 = kt * 128;
        if (tid < 128) mk[tid] = mask[k0 + tid];

        // ---- QK phase: K dim-chunks of 32, double-buffered ----
#pragma unroll
        for (int i = 0; i < 4; i++) {
            int idx = tid + i * 256;
            int pl = idx >> 9, j = idx & 511;
            int r = j >> 2, c4 = j & 3;
            const uint32_t* src = (pl ? klp : kh) +
                                  (size_t)(k0 + r) * 512 + h * 128 + c4 * 4;
            cp16(smem_u32(Kb + pl * FL_KU + r * 20 + c4 * 4), src);
        }
        CP_COMMIT();

        float accS[2][4][4];
#pragma unroll
        for (int mf = 0; mf < 2; mf++)
#pragma unroll
            for (int nf = 0; nf < 4; nf++)
#pragma unroll
                for (int j = 0; j < 4; j++) accS[mf][nf][j] = 0.f;

        for (int dc = 0; dc < 8; dc++) {
            if (dc < 7) {
                const int b2s = (dc + 1) & 1;
#pragma unroll
                for (int i = 0; i < 4; i++) {
                    int idx = tid + i * 256;
                    int pl = idx >> 9, j = idx & 511;
                    int r = j >> 2, c4 = j & 3;
                    const uint32_t* src = (pl ? klp : kh) +
                        (size_t)(k0 + r) * 512 + h * 128 + (dc + 1) * 16 + c4 * 4;
                    cp16(smem_u32(Kb + b2s * 2 * FL_KU + pl * FL_KU +
                                  r * 20 + c4 * 4), src);
                }
                CP_COMMIT();
                CP_WAIT1();
            } else {
                CP_WAIT0();
            }
            __syncthreads();
            const uint32_t* Kph = Kb + (dc & 1) * 2 * FL_KU;
            const uint32_t* Kpl = Kph + FL_KU;
#pragma unroll
            for (int kk = 0; kk < 2; kk++) {
                const int kof = kk * 8 + qc;
                uint32_t qa_h[2][4], qa_l[2][4], kb_h[4][2], kb_l[4][2];
#pragma unroll
                for (int mf = 0; mf < 2; mf++) {
                    int base = (wm * 32 + 16 * mf + qr) * 132 + dc * 16 + kof;
                    qa_h[mf][0] = Qh[base];
                    qa_h[mf][1] = Qh[base + 8 * 132];
                    qa_h[mf][2] = Qh[base + 4];
                    qa_h[mf][3] = Qh[base + 8 * 132 + 4];
                    qa_l[mf][0] = Ql[base];
                    qa_l[mf][1] = Ql[base + 8 * 132];
                    qa_l[mf][2] = Ql[base + 4];
                    qa_l[mf][3] = Ql[base + 8 * 132 + 4];
                }
#pragma unroll
                for (int nf = 0; nf < 4; nf++) {
                    int base = (wn * 32 + nf * 8 + qr) * 20 + kof;
                    kb_h[nf][0] = Kph[base]; kb_h[nf][1] = Kph[base + 4];
                    kb_l[nf][0] = Kpl[base]; kb_l[nf][1] = Kpl[base + 4];
                }
#pragma unroll
                for (int mf = 0; mf < 2; mf++)
#pragma unroll
                    for (int nf = 0; nf < 4; nf++)
                        mma16816(accS[mf][nf], qa_h[mf], kb_h[nf]);
#pragma unroll
                for (int mf = 0; mf < 2; mf++)
#pragma unroll
                    for (int nf = 0; nf < 4; nf++)
                        mma16816(accS[mf][nf], qa_h[mf], kb_l[nf]);
#pragma unroll
                for (int mf = 0; mf < 2; mf++)
#pragma unroll
                    for (int nf = 0; nf < 4; nf++)
                        mma16816(accS[mf][nf], qa_l[mf], kb_h[nf]);
            }
            __syncthreads();
        }

        // ---- mask + online softmax ----
#pragma unroll
        for (int mf = 0; mf < 2; mf++)
#pragma unroll
            for (int nf = 0; nf < 4; nf++) {
                int cb = wn * 32 + nf * 8 + qc * 2;
                if (!mk[cb])     { accS[mf][nf][0] = -1e9f; accS[mf][nf][2] = -1e9f; }
                if (!mk[cb + 1]) { accS[mf][nf][1] = -1e9f; accS[mf][nf][3] = -1e9f; }
            }
#pragma unroll
        for (int mf = 0; mf < 2; mf++)
#pragma unroll
            for (int h2 = 0; h2 < 2; h2++) {
                float v = -3.0e38f;
#pragma unroll
                for (int nf = 0; nf < 4; nf++)
                    v = fmaxf(v, fmaxf(accS[mf][nf][2 * h2],
                                       accS[mf][nf][2 * h2 + 1]));
                v = fmaxf(v, __shfl_xor_sync(0xffffffffu, v, 1));
                v = fmaxf(v, __shfl_xor_sync(0xffffffffu, v, 2));
                if (qc == 0)
                    red[wn * 64 + wm * 32 + 16 * mf + 8 * h2 + qr] = v;
            }
        __syncthreads();
        if (tid < 64) {
            float tm = fmaxf(fmaxf(red[tid], red[64 + tid]),
                             fmaxf(red[128 + tid], red[192 + tid]));
            float mo = mS[tid], mn = fmaxf(mo, tm);
            aS[tid] = __expf(mo - mn);
            mS[tid] = mn;
        }
        __syncthreads();

        // prefetch V chunk 0 (independent of P)
#pragma unroll
        for (int i = 0; i < 8; i++) {
            int idx = tid + i * 256;
            int pl = idx >> 10, j = idx & 1023;
            int r = j >> 4, c4 = j & 15;
            int dim = h * 256 + (r >> 4) * 64 + (r & 15);
            const uint32_t* src = (pl ? vlp : vh) +
                                  (size_t)dim * 2048 + kt * 64 + c4 * 4;
            cp16(smem_u32(Vb + pl * FL_VU + r * 68 + c4 * 4), src);
        }
        CP_COMMIT();

        // p, row sums, write P (bf16 hi/lo) to smem
#pragma unroll
        for (int mf = 0; mf < 2; mf++)
#pragma unroll
            for (int h2 = 0; h2 < 2; h2++) {
                int row = wm * 32 + 16 * mf + 8 * h2 + qr;
                float mn = mS[row];
                float s = 0.f;
#pragma unroll
                for (int nf = 0; nf < 4; nf++) {
                    float p0 = __expf(accS[mf][nf][2 * h2] - mn);
                    float p1 = __expf(accS[mf][nf][2 * h2 + 1] - mn);
                    s += p0 + p1;
                    uint32_t hh, ll;
                    split2(p0, p1, hh, ll);
                    int pc = row * 68 + wn * 16 + nf * 4 + qc;
                    Pb[pc] = hh;
                    Pb[FL_PU + pc] = ll;
                }
                s += __shfl_xor_sync(0xffffffffu, s, 1);
                s += __shfl_xor_sync(0xffffffffu, s, 2);
                if (qc == 0) red[wn * 64 + row] = s;
            }
        __syncthreads();
        if (tid < 64)
            lS[tid] = lS[tid] * aS[tid] +
                      (red[tid] + red[64 + tid] + red[128 + tid] + red[192 + tid]);

        // rescale O
#pragma unroll
        for (int mf = 0; mf < 2; mf++) {
            float a0 = aS[wm * 32 + 16 * mf + qr];
            float a1 = aS[wm * 32 + 16 * mf + 8 + qr];
#pragma unroll
            for (int g = 0; g < 8; g++) {
                accO[mf][g][0] *= a0; accO[mf][g][1] *= a0;
                accO[mf][g][2] *= a1; accO[mf][g][3] *= a1;
            }
        }
        __syncthreads();

        // ---- PV phase: V dim-chunks of 16 per warp, double-buffered ----
        for (int vc = 0; vc < 4; vc++) {
            if (vc < 3) {
                const int b2s = (vc + 1) & 1;
#pragma unroll
                for (int i = 0; i < 8; i++) {
                    int idx = tid + i * 256;
                    int pl = idx >> 10, j = idx & 1023;
                    int r = j >> 4, c4 = j & 15;
                    int dim = h * 256 + (r >> 4) * 64 + (vc + 1) * 16 + (r & 15);
                    const uint32_t* src = (pl ? vlp : vh) +
                                          (size_t)dim * 2048 + kt * 64 + c4 * 4;
                    cp16(smem_u32(Vb + b2s * 2 * FL_VU + pl * FL_VU +
                                  r * 68 + c4 * 4), src);
                }
                CP_COMMIT();
                CP_WAIT1();
            } else {
                CP_WAIT0();
            }
            __syncthreads();
            const uint32_t* Vph = Vb + (vc & 1) * 2 * FL_VU;
            const uint32_t* Vpl = Vph + FL_VU;
#pragma unroll
            for (int s = 0; s < 8; s++) {
                uint32_t pa_h[2][4], pa_l[2][4], vb_h[2][2], vb_l[2][2];
#pragma unroll
                for (int mf = 0; mf < 2; mf++) {
                    int base = (wm * 32 + 16 * mf + qr) * 68 + s * 8 + qc;
                    pa_h[mf][0] = Pb[base];
                    pa_h[mf][1] = Pb[base + 8 * 68];
                    pa_h[mf][2] = Pb[base + 4];
                    pa_h[mf][3] = Pb[base + 8 * 68 + 4];
                    pa_l[mf][0] = Pb[FL_PU + base];
                    pa_l[mf][1] = Pb[FL_PU + base + 8 * 68];
                    pa_l[mf][2] = Pb[FL_PU + base + 4];
                    pa_l[mf][3] = Pb[FL_PU + base + 8 * 68 + 4];
                }
#pragma unroll
                for (int nf = 0; nf < 2; nf++) {
                    int base = (wn * 16 + nf * 8 + qr) * 68 + s * 8 + qc;
                    vb_h[nf][0] = Vph[base]; vb_h[nf][1] = Vph[base + 4];
                    vb_l[nf][0] = Vpl[base]; vb_l[nf][1] = Vpl[base + 4];
                }
#pragma unroll
                for (int mf = 0; mf < 2; mf++)
#pragma unroll
                    for (int nf = 0; nf < 2; nf++)
                        mma16816(accO[mf][vc * 2 + nf], pa_h[mf], vb_h[nf]);
#pragma unroll
                for (int mf = 0; mf < 2; mf++)
#pragma unroll
                    for (int nf = 0; nf < 2; nf++)
                        mma16816(accO[mf][vc * 2 + nf], pa_h[mf], vb_l[nf]);
#pragma unroll
                for (int mf = 0; mf < 2; mf++)
#pragma unroll
                    for (int nf = 0; nf < 2; nf++)
                        mma16816(accO[mf][vc * 2 + nf], pa_l[mf], vb_h[nf]);
            }
            __syncthreads();
        }
    }

    // ---- epilogue: ctx = O / l ----
#pragma unroll
    for (int mf = 0; mf < 2; mf++) {
        const int r0 = wm * 32 + 16 * mf + qr;
        const float i0 = 1.0f / lS[r0];
        const float i1 = 1.0f / lS[r0 + 8];
#pragma unroll
        for (int g = 0; g < 8; g++) {
            const int col = h * 256 + wn * 64 + g * 8 + qc * 2;
            float2 o0 = {accO[mf][g][0] * i0, accO[mf][g][1] * i0};
            float2 o1 = {accO[mf][g][2] * i1, accO[mf][g][3] * i1};
            *(float2*)&ctx[(long)(q0 + r0) * DMODEL + col] = o0;
            *(float2*)&ctx[(long)(q0 + r0 + 8) * DMODEL + col] = o1;
        }
    }
}

// ---------------------------------------------------------------------------
extern "C" void kernel_launch(void* const* d_in, const int* in_sizes, int n_in,
                              void* d_out, int out_size)
{
    const float* q  = (const float*)d_in[0];
    const float* k  = (const float*)d_in[1];
    const float* v  = (const float*)d_in[2];
    const float* w1 = (const float*)d_in[3];
    const float* b1 = (const float*)d_in[4];
    const float* w2 = (const float*)d_in[5];
    const float* b2 = (const float*)d_in[6];
    const float* wq = (const float*)d_in[7];
    const float* bq = (const float*)d_in[8];
    const float* wk = (const float*)d_in[9];
    const float* bk = (const float*)d_in[10];
    const float* wv = (const float*)d_in[11];
    const float* bv = (const float*)d_in[12];
    const float* wo = (const float*)d_in[13];
    const float* bo = (const float*)d_in[14];
    float* out = (float*)d_out;

    float *hh, *ctx, *w1t, *wqt, *wkt, *wvt, *wot;
    uint32_t *qph, *qpl, *kph, *kpl, *vph, *vpl, *vth, *vtl;
    int* msk;
    cudaGetSymbolAddress((void**)&hh,  g_h);
    cudaGetSymbolAddress((void**)&msk, g_mask);
    cudaGetSymbolAddress((void**)&ctx, g_ctx);
    cudaGetSymbolAddress((void**)&w1t, g_w1t);
    cudaGetSymbolAddress((void**)&wqt, g_wqt);
    cudaGetSymbolAddress((void**)&wkt, g_wkt);
    cudaGetSymbolAddress((void**)&wvt, g_wvt);
    cudaGetSymbolAddress((void**)&wot, g_wot);
    cudaGetSymbolAddress((void**)&qph, g_qph);
    cudaGetSymbolAddress((void**)&qpl, g_qpl);
    cudaGetSymbolAddress((void**)&kph, g_kph);
    cudaGetSymbolAddress((void**)&kpl, g_kpl);
    cudaGetSymbolAddress((void**)&vph, g_vph);
    cudaGetSymbolAddress((void**)&vpl, g_vpl);
    cudaGetSymbolAddress((void**)&vth, g_vth);
    cudaGetSymbolAddress((void**)&vtl, g_vtl);

    cudaFuncSetAttribute(gemm_bf<EPI_RELU, 0>,
        cudaFuncAttributeMaxDynamicSharedMemorySize, SMEM_BYTES);
    cudaFuncSetAttribute(gemm_bf<EPI_QSCALE, 1>,
        cudaFuncAttributeMaxDynamicSharedMemorySize, SMEM_BYTES);
    cudaFuncSetAttribute(gemm_bf<EPI_BIAS, 1>,
        cudaFuncAttributeMaxDynamicSharedMemorySize, SMEM_BYTES);
    cudaFuncSetAttribute(gemm_bf<EPI_ROWMASK, 0>,
        cudaFuncAttributeMaxDynamicSharedMemorySize, SMEM_BYTES);
    cudaFuncSetAttribute(flash_k,
        cudaFuncAttributeMaxDynamicSharedMemorySize, FL_SMEM_B);

    dim3 tb(32, 8);
    transpose_k<<<dim3(DHID / 32, DMODEL / 32), tb>>>(w1, w1t, DMODEL, DHID);
    transpose_k<<<dim3(32, 32), tb>>>(wq, wqt, DMODEL, DMODEL);
    transpose_k<<<dim3(32, 32), tb>>>(wk, wkt, DMODEL, DMODEL);
    transpose_k<<<dim3(32, 32), tb>>>(wv, wvt, DMODEL, DMODEL);
    transpose_k<<<dim3(32, 32), tb>>>(wo, wot, DMODEL, DMODEL);

    // 1) predictor hidden: h = relu(q @ w1 + b1)
    gemm_bf<EPI_RELU, 0><<<dim3(DHID / 128, NTOK / 128), 256, SMEM_BYTES>>>(
        q, DMODEL, w1t, DMODEL, hh, nullptr, nullptr, DHID, DMODEL, b1,
        nullptr, 0.f);
    // 2) token mask
    score_k<<<NTOK / 8, 256>>>(hh, w2, b2, msk);
    // 3) projections -> bf16 hi/lo planes (softmax scale folded into Q)
    gemm_bf<EPI_QSCALE, 1><<<dim3(8, 32), 256, SMEM_BYTES>>>(
        q, DMODEL, wqt, DMODEL, nullptr, qph, qpl, DMODEL, DMODEL, bq,
        nullptr, 0.0625f);
    gemm_bf<EPI_BIAS, 1><<<dim3(8, 32), 256, SMEM_BYTES>>>(
        k, DMODEL, wkt, DMODEL, nullptr, kph, kpl, DMODEL, DMODEL, bk,
        nullptr, 0.f);
    gemm_bf<EPI_BIAS, 1><<<dim3(8, 32), 256, SMEM_BYTES>>>(
        v, DMODEL, wvt, DMODEL, nullptr, vph, vpl, DMODEL, DMODEL, bv,
        nullptr, 0.f);
    // 4) transpose V planes -> [1024][4096]
    transpose_bf<<<dim3(DMODEL / 32, NTOK / 32, 2), tb>>>(
        (const uint16_t*)vph, (const uint16_t*)vpl,
        (uint16_t*)vth, (uint16_t*)vtl, NTOK, DMODEL);
    // 5) fused attention (QK^T + key mask + online softmax + PV)
    flash_k<<<dim3(NTOK / 64, NHEADS), 256, FL_SMEM_B>>>(
        qph, qpl, kph, kpl, vth, vtl, msk, ctx);
    // 6) out = rowmask(ctx @ wo + bo)
    gemm_bf<EPI_ROWMASK, 0><<<dim3(8, 32), 256, SMEM_BYTES>>>(
        ctx, DMODEL, wot, DMODEL, out, nullptr, nullptr, DMODEL, DMODEL, bo,
        msk, 0.f);
}

// round 6
// speedup vs baseline: 1.2856x; 1.2856x over previous
#include <cuda_runtime.h>
#include <cstdint>
#include <math.h>

#define NTOK   4096
#define DMODEL 1024
#define DHID   256
#define NHEADS 4
#define HDIM   256

// ---------------- scratch (__device__ globals; no allocation allowed) -------
__device__ float g_h  [NTOK * DHID];
__device__ int   g_mask[NTOK];
__device__ float g_qp [NTOK * DMODEL];
__device__ float g_kp [NTOK * DMODEL];
__device__ float g_vp [NTOK * DMODEL];
__device__ float g_ctx[NTOK * DMODEL];
__device__ float g_w1t[DHID * DMODEL];
__device__ float g_wqt[DMODEL * DMODEL];
__device__ float g_wkt[DMODEL * DMODEL];
__device__ float g_wvt[DMODEL * DMODEL];
__device__ float g_wot[DMODEL * DMODEL];
__device__ float g_vpt[DMODEL * NTOK];
__device__ float g_S  [(size_t)NHEADS * NTOK * NTOK];   // 268MB

// ---------------- bf16 helpers ----------------------------------------------
__device__ __forceinline__ uint32_t pack2(float x0, float x1) {
    uint32_t r;
    asm("cvt.rn.bf16x2.f32 %0, %1, %2;" : "=r"(r) : "f"(x1), "f"(x0));
    return r;
}
__device__ __forceinline__ void split2(float x0, float x1,
                                       uint32_t& h, uint32_t& l) {
    uint32_t hb = pack2(x0, x1);
    float f0 = __uint_as_float(hb << 16);
    float f1 = __uint_as_float(hb & 0xffff0000u);
    l = pack2(x0 - f0, x1 - f1);
    h = hb;
}
__device__ __forceinline__ void mma16816(float* c, const uint32_t* a,
                                         const uint32_t* b) {
    asm volatile(
        "mma.sync.aligned.m16n8k16.row.col.f32.bf16.bf16.f32 "
        "{%0,%1,%2,%3}, {%4,%5,%6,%7}, {%8,%9}, {%0,%1,%2,%3};"
        : "+f"(c[0]), "+f"(c[1]), "+f"(c[2]), "+f"(c[3])
        : "r"(a[0]), "r"(a[1]), "r"(a[2]), "r"(a[3]), "r"(b[0]), "r"(b[1]));
}
__device__ __forceinline__ uint32_t smem_u32(const void* p) {
    uint32_t a;
    asm("{ .reg .u64 t; cvta.to.shared.u64 t, %1; cvt.u32.u64 %0, t; }"
        : "=r"(a) : "l"(p));
    return a;
}
__device__ __forceinline__ void ldsm4(uint32_t& r0, uint32_t& r1,
                                      uint32_t& r2, uint32_t& r3,
                                      uint32_t addr) {
    asm volatile("ldmatrix.sync.aligned.m8n8.x4.shared.b16 {%0,%1,%2,%3}, [%4];"
                 : "=r"(r0), "=r"(r1), "=r"(r2), "=r"(r3) : "r"(addr));
}

// ---------------- unified 3xBF16 tensor-core GEMM ---------------------------
// D[M,N] = A[M,K] @ B[N,K]^T (+ epilogue). CTA 128x128, K-chunk 32, 8 warps.
enum { EPI_RAW = 0, EPI_BIAS, EPI_RELU, EPI_QSCALE, EPI_KEYMASK, EPI_ROWMASK };

#define SROW   20                      // u32 per smem row (16 data + 4 pad)
#define STG_U  (128 * SROW)
#define STG_B  (4 * STG_U * 4)         // Ah|Al|Bh|Bl = 40960 bytes
#define SMEM_BYTES (2 * STG_B)

__device__ __forceinline__ void ldg_chunk(const float* __restrict__ Arow,
                                          int lda,
                                          const float* __restrict__ Brow,
                                          int ldb, int k0, int tid,
                                          float4* av, float4* bv) {
#pragma unroll
    for (int i = 0; i < 4; i++) {
        int idx = tid + i * 256;
        int r = idx >> 3, c4 = idx & 7;
        av[i] = *(const float4*)(Arow + (long)r * lda + k0 + c4 * 4);
        bv[i] = *(const float4*)(Brow + (long)r * ldb + k0 + c4 * 4);
    }
}
__device__ __forceinline__ void sts_chunk(uint32_t* st, int tid,
                                          const float4* av, const float4* bv) {
    uint32_t* Ah = st;
    uint32_t* Al = st + STG_U;
    uint32_t* Bh = st + 2 * STG_U;
    uint32_t* Bl = st + 3 * STG_U;
#pragma unroll
    for (int i = 0; i < 4; i++) {
        int idx = tid + i * 256;
        int r = idx >> 3, c4 = idx & 7;
        uint32_t h01, l01, h23, l23;
        split2(av[i].x, av[i].y, h01, l01);
        split2(av[i].z, av[i].w, h23, l23);
        int o = r * SROW + c4 * 2;
        Ah[o] = h01; Ah[o + 1] = h23;
        Al[o] = l01; Al[o + 1] = l23;
        split2(bv[i].x, bv[i].y, h01, l01);
        split2(bv[i].z, bv[i].w, h23, l23);
        Bh[o] = h01; Bh[o + 1] = h23;
        Bl[o] = l01; Bl[o + 1] = l23;
    }
}

template <int EPI>
__global__ __launch_bounds__(256, 1) void gemm_bf(
    const float* __restrict__ A, int lda, long aZ,
    const float* __restrict__ B, int ldb, long bZ,
    float* __restrict__ C, int ldc, long cZ,
    int K, const float* __restrict__ bias,
    const int* __restrict__ mask, float scale)
{
    extern __shared__ __align__(16) char smem[];
    const int tid = threadIdx.x;
    const int wid = tid >> 5, lane = tid & 31;
    const int wm = wid & 3, wn = wid >> 2;      // 4x2 warp grid
    const int qr = lane >> 2, qc = lane & 3;
    const int bm = blockIdx.y * 128, bn = blockIdx.x * 128;

    A += blockIdx.z * aZ;
    B += blockIdx.z * bZ;
    C += blockIdx.z * cZ;
    const float* Arow = A + (long)bm * lda;
    const float* Brow = B + (long)bn * ldb;

    // ldmatrix per-lane offsets (u32 units within one plane sub-array)
    const int a_off = (wm * 32 + ((lane >> 3) & 1) * 8 + (lane & 7)) * SROW +
                      (lane >> 4) * 4;            // + mf*16*SROW
    const int b_off = (wn * 64 + (lane >> 4) * 8 + (lane & 7)) * SROW +
                      ((lane >> 3) & 1) * 4;      // + p*16*SROW

    float acc[2][8][4];
#pragma unroll
    for (int mf = 0; mf < 2; mf++)
#pragma unroll
        for (int nf = 0; nf < 8; nf++)
#pragma unroll
            for (int j = 0; j < 4; j++) acc[mf][nf][j] = 0.f;

    const int nc = K / 32;
    float4 av[4], bv[4];
    ldg_chunk(Arow, lda, Brow, ldb, 0, tid, av, bv);
    sts_chunk((uint32_t*)smem, tid, av, bv);
    __syncthreads();

    for (int c = 0; c < nc; c++) {
        if (c + 1 < nc)
            ldg_chunk(Arow, lda, Brow, ldb, (c + 1) * 32, tid, av, bv);
        const uint32_t sb = smem_u32(smem + (c & 1) * STG_B);
#pragma unroll
        for (int kk = 0; kk < 2; kk++) {
            uint32_t ah[2][4], al[2][4], bh[8][2], bl[8][2];
#pragma unroll
            for (int mf = 0; mf < 2; mf++) {
                uint32_t ao = sb + (uint32_t)(a_off + mf * 16 * SROW + kk * 8) * 4;
                ldsm4(ah[mf][0], ah[mf][1], ah[mf][2], ah[mf][3], ao);
                ldsm4(al[mf][0], al[mf][1], al[mf][2], al[mf][3],
                      ao + STG_U * 4);
            }
#pragma unroll
            for (int p = 0; p < 4; p++) {
                uint32_t bo = sb + 2 * STG_U * 4 +
                              (uint32_t)(b_off + p * 16 * SROW + kk * 8) * 4;
                ldsm4(bh[2 * p][0], bh[2 * p][1],
                      bh[2 * p + 1][0], bh[2 * p + 1][1], bo);
                ldsm4(bl[2 * p][0], bl[2 * p][1],
                      bl[2 * p + 1][0], bl[2 * p + 1][1], bo + STG_U * 4);
            }
#pragma unroll
            for (int mf = 0; mf < 2; mf++)
#pragma unroll
                for (int nf = 0; nf < 8; nf++) {
                    mma16816(acc[mf][nf], ah[mf], bh[nf]);
                    mma16816(acc[mf][nf], ah[mf], bl[nf]);
                    mma16816(acc[mf][nf], al[mf], bh[nf]);
                }
        }
        __syncthreads();
        if (c + 1 < nc) {
            sts_chunk((uint32_t*)(smem + ((c + 1) & 1) * STG_B), tid, av, bv);
            __syncthreads();
        }
    }

#pragma unroll
    for (int mf = 0; mf < 2; mf++) {
        const int r0 = bm + wm * 32 + mf * 16 + qr;
        const int r1 = r0 + 8;
        int keep0 = 1, keep1 = 1;
        if (EPI == EPI_ROWMASK) { keep0 = mask[r0]; keep1 = mask[r1]; }
#pragma unroll
        for (int nf = 0; nf < 8; nf++) {
            const int cc = bn + wn * 64 + nf * 8 + qc * 2;
            float v0 = acc[mf][nf][0], v1 = acc[mf][nf][1];
            float v2 = acc[mf][nf][2], v3 = acc[mf][nf][3];
            if (EPI == EPI_BIAS || EPI == EPI_RELU || EPI == EPI_QSCALE ||
                EPI == EPI_ROWMASK) {
                float b0 = bias[cc], b1 = bias[cc + 1];
                v0 += b0; v1 += b1; v2 += b0; v3 += b1;
            }
            if (EPI == EPI_RELU) {
                v0 = fmaxf(v0, 0.f); v1 = fmaxf(v1, 0.f);
                v2 = fmaxf(v2, 0.f); v3 = fmaxf(v3, 0.f);
            }
            if (EPI == EPI_QSCALE) {
                v0 *= scale; v1 *= scale; v2 *= scale; v3 *= scale;
            }
            if (EPI == EPI_KEYMASK) {
                if (!mask[cc])     { v0 = -1e9f; v2 = -1e9f; }
                if (!mask[cc + 1]) { v1 = -1e9f; v3 = -1e9f; }
            }
            if (EPI == EPI_ROWMASK) {
                if (!keep0) { v0 = 0.f; v1 = 0.f; }
                if (!keep1) { v2 = 0.f; v3 = 0.f; }
            }
            float2 o0 = {v0, v1}, o1 = {v2, v3};
            *(float2*)&C[(long)r0 * ldc + cc] = o0;
            *(float2*)&C[(long)r1 * ldc + cc] = o1;
        }
    }
}

// ---------------- transpose: out[C][R] = in[R][C]^T --------------------------
__global__ void transpose_k(const float* __restrict__ in, float* __restrict__ out,
                            int R, int C)
{
    __shared__ float t[32][33];
    const int bx = blockIdx.x * 32, by = blockIdx.y * 32;
#pragma unroll
    for (int j = 0; j < 32; j += 8)
        t[threadIdx.y + j][threadIdx.x] =
            in[(long)(by + threadIdx.y + j) * C + bx + threadIdx.x];
    __syncthreads();
#pragma unroll
    for (int j = 0; j < 32; j += 8)
        out[(long)(bx + threadIdx.y + j) * R + by + threadIdx.x] =
            t[threadIdx.x][threadIdx.y + j];
}

// ---------------- mask: sigmoid(h @ w2 + b2) > 0.15 --------------------------
__global__ void score_k(const float* __restrict__ h, const float* __restrict__ w2,
                        const float* __restrict__ b2, int* __restrict__ mask)
{
    const int warp = (blockIdx.x * blockDim.x + threadIdx.x) >> 5;
    const int lane = threadIdx.x & 31;
    if (warp >= NTOK) return;
    const float* hr = h + warp * DHID;
    float s = 0.f;
#pragma unroll
    for (int i = 0; i < DHID / 32; i++)
        s += hr[lane + i * 32] * w2[lane + i * 32];
#pragma unroll
    for (int o = 16; o; o >>= 1) s += __shfl_xor_sync(0xffffffffu, s, o);
    if (lane == 0) {
        float sig = 1.0f / (1.0f + expf(-(s + b2[0])));
        mask[warp] = (sig > 0.15f) ? 1 : 0;
    }
}

// ---------------- row softmax over 4096 keys (in place) ----------------------
__global__ __launch_bounds__(256) void softmax_k(float* __restrict__ S)
{
    __shared__ float cache[NTOK];
    __shared__ float red[256];
    float* Sr = S + ((size_t)blockIdx.y * NTOK + blockIdx.x) * NTOK;
    const int tid = threadIdx.x;

    float m = -3.4e38f;
#pragma unroll
    for (int i = 0; i < 4; i++) {
        float4 v = *(const float4*)&Sr[(tid + i * 256) * 4];
        m = fmaxf(m, fmaxf(fmaxf(v.x, v.y), fmaxf(v.z, v.w)));
    }
    red[tid] = m;
    __syncthreads();
    for (int s = 128; s; s >>= 1) {
        if (tid < s) red[tid] = fmaxf(red[tid], red[tid + s]);
        __syncthreads();
    }
    m = red[0];
    __syncthreads();

    float sum = 0.f;
#pragma unroll
    for (int i = 0; i < 4; i++) {
        int f4 = tid + i * 256;
        float4 v = *(const float4*)&Sr[f4 * 4];
        float4 p;
        p.x = __expf(v.x - m); p.y = __expf(v.y - m);
        p.z = __expf(v.z - m); p.w = __expf(v.w - m);
        *(float4*)&cache[f4 * 4] = p;
        sum += p.x + p.y + p.z + p.w;
    }
    red[tid] = sum;
    __syncthreads();
    for (int s = 128; s; s >>= 1) {
        if (tid < s) red[tid] += red[tid + s];
        __syncthreads();
    }
    const float inv = 1.0f / red[0];
#pragma unroll
    for (int i = 0; i < 4; i++) {
        int f4 = tid + i * 256;
        float4 p = *(float4*)&cache[f4 * 4];
        p.x *= inv; p.y *= inv; p.z *= inv; p.w *= inv;
        *(float4*)&Sr[f4 * 4] = p;
    }
}

// ---------------------------------------------------------------------------
extern "C" void kernel_launch(void* const* d_in, const int* in_sizes, int n_in,
                              void* d_out, int out_size)
{
    const float* q  = (const float*)d_in[0];
    const float* k  = (const float*)d_in[1];
    const float* v  = (const float*)d_in[2];
    const float* w1 = (const float*)d_in[3];
    const float* b1 = (const float*)d_in[4];
    const float* w2 = (const float*)d_in[5];
    const float* b2 = (const float*)d_in[6];
    const float* wq = (const float*)d_in[7];
    const float* bq = (const float*)d_in[8];
    const float* wk = (const float*)d_in[9];
    const float* bk = (const float*)d_in[10];
    const float* wv = (const float*)d_in[11];
    const float* bv = (const float*)d_in[12];
    const float* wo = (const float*)d_in[13];
    const float* bo = (const float*)d_in[14];
    float* out = (float*)d_out;

    float *hh, *qp, *kp, *vp, *ctx, *w1t, *wqt, *wkt, *wvt, *wot, *vpt, *S;
    int* msk;
    cudaGetSymbolAddress((void**)&hh,  g_h);
    cudaGetSymbolAddress((void**)&msk, g_mask);
    cudaGetSymbolAddress((void**)&qp,  g_qp);
    cudaGetSymbolAddress((void**)&kp,  g_kp);
    cudaGetSymbolAddress((void**)&vp,  g_vp);
    cudaGetSymbolAddress((void**)&ctx, g_ctx);
    cudaGetSymbolAddress((void**)&w1t, g_w1t);
    cudaGetSymbolAddress((void**)&wqt, g_wqt);
    cudaGetSymbolAddress((void**)&wkt, g_wkt);
    cudaGetSymbolAddress((void**)&wvt, g_wvt);
    cudaGetSymbolAddress((void**)&wot, g_wot);
    cudaGetSymbolAddress((void**)&vpt, g_vpt);
    cudaGetSymbolAddress((void**)&S,   g_S);

    cudaFuncSetAttribute(gemm_bf<EPI_RAW>,
        cudaFuncAttributeMaxDynamicSharedMemorySize, SMEM_BYTES);
    cudaFuncSetAttribute(gemm_bf<EPI_BIAS>,
        cudaFuncAttributeMaxDynamicSharedMemorySize, SMEM_BYTES);
    cudaFuncSetAttribute(gemm_bf<EPI_RELU>,
        cudaFuncAttributeMaxDynamicSharedMemorySize, SMEM_BYTES);
    cudaFuncSetAttribute(gemm_bf<EPI_QSCALE>,
        cudaFuncAttributeMaxDynamicSharedMemorySize, SMEM_BYTES);
    cudaFuncSetAttribute(gemm_bf<EPI_KEYMASK>,
        cudaFuncAttributeMaxDynamicSharedMemorySize, SMEM_BYTES);
    cudaFuncSetAttribute(gemm_bf<EPI_ROWMASK>,
        cudaFuncAttributeMaxDynamicSharedMemorySize, SMEM_BYTES);

    dim3 tb(32, 8);
    transpose_k<<<dim3(DHID / 32, DMODEL / 32), tb>>>(w1, w1t, DMODEL, DHID);
    transpose_k<<<dim3(32, 32), tb>>>(wq, wqt, DMODEL, DMODEL);
    transpose_k<<<dim3(32, 32), tb>>>(wk, wkt, DMODEL, DMODEL);
    transpose_k<<<dim3(32, 32), tb>>>(wv, wvt, DMODEL, DMODEL);
    transpose_k<<<dim3(32, 32), tb>>>(wo, wot, DMODEL, DMODEL);

    // 1) predictor hidden: h = relu(q @ w1 + b1)
    gemm_bf<EPI_RELU><<<dim3(DHID / 128, NTOK / 128), 256, SMEM_BYTES>>>(
        q, DMODEL, 0, w1t, DMODEL, 0, hh, DHID, 0, DMODEL, b1, nullptr, 0.f);
    // 2) token mask
    score_k<<<NTOK / 8, 256>>>(hh, w2, b2, msk);
    // 3) projections (softmax scale folded into qp)
    gemm_bf<EPI_QSCALE><<<dim3(8, 32), 256, SMEM_BYTES>>>(
        q, DMODEL, 0, wqt, DMODEL, 0, qp, DMODEL, 0, DMODEL, bq, nullptr,
        0.0625f);
    gemm_bf<EPI_BIAS><<<dim3(8, 32), 256, SMEM_BYTES>>>(
        k, DMODEL, 0, wkt, DMODEL, 0, kp, DMODEL, 0, DMODEL, bk, nullptr, 0.f);
    gemm_bf<EPI_BIAS><<<dim3(8, 32), 256, SMEM_BYTES>>>(
        v, DMODEL, 0, wvt, DMODEL, 0, vp, DMODEL, 0, DMODEL, bv, nullptr, 0.f);
    // 4) transpose V projection -> [1024][4096]
    transpose_k<<<dim3(DMODEL / 32, NTOK / 32), tb>>>(vp, vpt, NTOK, DMODEL);
    // 5) S[h] = qp @ kp^T, masked keys -> -1e9
    gemm_bf<EPI_KEYMASK><<<dim3(32, 32, NHEADS), 256, SMEM_BYTES>>>(
        qp, DMODEL, HDIM, kp, DMODEL, HDIM, S, NTOK, (long)NTOK * NTOK,
        HDIM, nullptr, msk, 0.f);
    // 6) softmax rows
    softmax_k<<<dim3(NTOK, NHEADS), 256>>>(S);
    // 7) ctx[h] = P @ V
    gemm_bf<EPI_RAW><<<dim3(HDIM / 128, 32, NHEADS), 256, SMEM_BYTES>>>(
        S, NTOK, (long)NTOK * NTOK, vpt, NTOK, (long)HDIM * NTOK,
        ctx, DMODEL, HDIM, NTOK, nullptr, nullptr, 0.f);
    // 8) out = rowmask(ctx @ wo + bo)
    gemm_bf<EPI_ROWMASK><<<dim3(8, 32), 256, SMEM_BYTES>>>(
        ctx, DMODEL, 0, wot, DMODEL, 0, out, DMODEL, 0, DMODEL, bo, msk, 0.f);
}